// round 9
// baseline (speedup 1.0000x reference)
#include <cuda_runtime.h>
#include <cuda_bf16.h>
#include <cstdint>

#define DEVINL __device__ __forceinline__

static constexpr int NN = 16384;   // nodes
static constexpr int DF = 256;     // feature dim == out dim
static constexpr int K2 = 1024;    // GEMM2 K: [f_hi | f_hi | f_lo | neigh]

// ---------------- scratch (device globals; no allocation allowed) -----------
__device__ __align__(128) uint8_t       g_fT8[(size_t)DF * NN];  // 4 MB  features^T e4m3
__device__ __align__(128) __nv_bfloat16 g_A2[(size_t)NN * K2];   // 32 MB GEMM2 A operand
__device__ __align__(128) __nv_bfloat16 g_B2[(size_t)DF * K2];   // 512 KB GEMM2 B operand

// ---------------- PTX helpers (all legal at compute_103 virtual arch) -------
DEVINL uint32_t smem_u32(const void* p) {
    uint32_t a;
    asm("{ .reg .u64 t; cvta.to.shared.u64 t, %1; cvt.u32.u64 %0, t; }"
        : "=r"(a) : "l"(p));
    return a;
}
DEVINL void cp16(uint32_t dst, const void* src) {
    asm volatile("cp.async.cg.shared.global [%0], [%1], 16;"
                 :: "r"(dst), "l"(src) : "memory");
}
DEVINL void cp_commit() { asm volatile("cp.async.commit_group;" ::: "memory"); }
template <int N> DEVINL void cp_wait() {
    asm volatile("cp.async.wait_group %0;" :: "n"(N) : "memory");
}
DEVINL void ldsm4(uint32_t* r, uint32_t a) {
    asm volatile("ldmatrix.sync.aligned.m8n8.x4.shared.b16 {%0,%1,%2,%3}, [%4];"
                 : "=r"(r[0]), "=r"(r[1]), "=r"(r[2]), "=r"(r[3]) : "r"(a));
}
DEVINL void sts128(uint32_t a, uint32_t x, uint32_t y, uint32_t z, uint32_t w) {
    asm volatile("st.shared.v4.b32 [%0], {%1,%2,%3,%4};"
                 :: "r"(a), "r"(x), "r"(y), "r"(z), "r"(w));
}
// bf16: m16n8k16.  fp8 e4m3: m16n8k32 — identical fragment register shapes.
DEVINL void mma_bf16(float* d, const uint32_t* a, uint32_t b0, uint32_t b1) {
    asm volatile(
        "mma.sync.aligned.m16n8k16.row.col.f32.bf16.bf16.f32 "
        "{%0,%1,%2,%3}, {%4,%5,%6,%7}, {%8,%9}, {%0,%1,%2,%3};"
        : "+f"(d[0]), "+f"(d[1]), "+f"(d[2]), "+f"(d[3])
        : "r"(a[0]), "r"(a[1]), "r"(a[2]), "r"(a[3]), "r"(b0), "r"(b1));
}
DEVINL void mma_fp8(float* d, const uint32_t* a, uint32_t b0, uint32_t b1) {
    asm volatile(
        "mma.sync.aligned.m16n8k32.row.col.f32.e4m3.e4m3.f32 "
        "{%0,%1,%2,%3}, {%4,%5,%6,%7}, {%8,%9}, {%0,%1,%2,%3};"
        : "+f"(d[0]), "+f"(d[1]), "+f"(d[2]), "+f"(d[3])
        : "r"(a[0]), "r"(a[1]), "r"(a[2]), "r"(a[3]), "r"(b0), "r"(b1));
}
DEVINL uint32_t packbf2(float x, float y) {
    __nv_bfloat162 h = __floats2bfloat162_rn(x, y);
    return *reinterpret_cast<uint32_t*>(&h);
}
// pack 4 floats -> 4 e4m3 bytes, little-endian order {a,b,c,d}
DEVINL uint32_t pack4_e4m3(float a, float b, float c, float d) {
    uint16_t lo, hi;
    asm("cvt.rn.satfinite.e4m3x2.f32 %0, %1, %2;" : "=h"(lo) : "f"(b), "f"(a));
    asm("cvt.rn.satfinite.e4m3x2.f32 %0, %1, %2;" : "=h"(hi) : "f"(d), "f"(c));
    return (uint32_t)lo | ((uint32_t)hi << 16);
}
DEVINL uint8_t f2e4m3(float x) {
    uint16_t t;
    asm("cvt.rn.satfinite.e4m3x2.f32 %0, %1, %2;" : "=h"(t) : "f"(0.f), "f"(x));
    return (uint8_t)t;
}
DEVINL float4 ldcs4(const float* p) {
    float4 v;
    asm volatile("ld.global.cs.v4.f32 {%0,%1,%2,%3}, [%4];"
                 : "=f"(v.x), "=f"(v.y), "=f"(v.z), "=f"(v.w) : "l"(p));
    return v;
}

// ---------------- prep kernels ----------------------------------------------

// features^T (e4m3) via tiled transpose. grid(512, 8), block(32, 8)
__global__ void prep_fT8(const float* __restrict__ f) {
    __shared__ uint8_t tile[32][33];
    const int i0 = blockIdx.x * 32, d0 = blockIdx.y * 32;
    const int tx = threadIdx.x, ty = threadIdx.y;
#pragma unroll
    for (int k = 0; k < 32; k += 8)
        tile[ty + k][tx] = f2e4m3(f[(size_t)(i0 + ty + k) * DF + d0 + tx]);
    __syncthreads();
#pragma unroll
    for (int k = 0; k < 32; k += 8)
        g_fT8[(size_t)(d0 + ty + k) * NN + i0 + tx] = tile[tx][ty + k];
}

// A2 = [f_hi | f_hi | f_lo | (neigh filled by GEMM1 epilogue)]
__global__ void __launch_bounds__(256) prep_A2(const float* __restrict__ f) {
    const int i = blockIdx.x, d = threadIdx.x;
    const float v = f[(size_t)i * DF + d];
    const __nv_bfloat16 h = __float2bfloat16(v);
    const size_t b = (size_t)i * K2;
    g_A2[b + d]       = h;
    g_A2[b + 256 + d] = h;
    g_A2[b + 512 + d] = __float2bfloat16(v - __bfloat162float(h));
}

// B2 = [W1_hi | W1_lo | W1_hi | W2]
__global__ void __launch_bounds__(256) prep_W(const float* __restrict__ W) {
    const int o = blockIdx.x, c = threadIdx.x;
    const float w1 = W[(size_t)o * 512 + c];
    const __nv_bfloat16 h = __float2bfloat16(w1);
    const size_t b = (size_t)o * K2;
    g_B2[b + c]       = h;
    g_B2[b + 256 + c] = __float2bfloat16(w1 - __bfloat162float(h));
    g_B2[b + 512 + c] = h;
    g_B2[b + 768 + c] = __float2bfloat16(W[(size_t)o * 512 + 256 + c]);
}

// ---------------- mma.sync GEMM ----------------------------------------------
// MODE 1 (FP8): BM=64, BN=256, BK=128 e4m3 (128B rows), 256 thr (8 warps,
//   2Mx4N, warp tile 32x64), 2 CTAs/SM, KT=128.
//   C = e4m3(adj) @ e4m3(f)^T; fused f32 row-sum -> inv_deg; epilogue scales,
//   writes bf16 neigh into g_A2[:, 768:1024]. A: 2-stage LDG+cvt->STS,
//   B: 3-stage cp.async per-tile groups, wait_group<1>.
// MODE 2 (BF16): BM=128, BN=256, BK=64 bf16 (128B rows), 512 thr, 4-stage.
//   C = A2 @ B2^T (K=1024 hi/lo split); epilogue writes fp32 out.
// Both modes: identical 128B-row SW128 swizzle and identical ldmatrix
// addressing (16B chunk = k16 fp8 or k8 bf16; chunk pair per mma k-step).
static constexpr int BN = 256;
static constexpr int BBYTES = BN * 128;                      // 32 KB / stage

template <int MODE>
__global__ void __launch_bounds__((MODE == 1) ? 256 : 512, (MODE == 1) ? 2 : 1)
gemm_mma(float* __restrict__ outF, const float* __restrict__ adjF) {
    constexpr int  THREADS = (MODE == 1) ? 256 : 512;
    constexpr int  BMm     = (MODE == 1) ? 64  : 128;
    constexpr int  BK      = (MODE == 1) ? 128 : 64;    // elems; 128B rows both
    constexpr int  KT      = (MODE == 1) ? (NN / 128) : (K2 / 64);
    constexpr int  ASTG    = (MODE == 1) ? 2 : 4;
    constexpr int  BSTG    = (MODE == 1) ? 3 : 4;
    constexpr int  PREF    = (MODE == 1) ? 2 : 3;   // groups committed ahead
    constexpr int  ABYTES  = BMm * 128;             // 8 KB / 16 KB
    constexpr uint32_t A_OFF = 0;
    constexpr uint32_t B_OFF = ASTG * ABYTES;

    extern __shared__ char smraw[];
    __shared__ float sdeg[BMm];
    const uint32_t sb = (smem_u32(smraw) + 127u) & ~127u;

    const int tid  = threadIdx.x;
    const int lane = tid & 31;
    const int w    = tid >> 5;
    const int wm   = w >> 2;            // M dir: mode1 0..1, mode2 0..3
    const int wn   = w & 3;             // N dir: 0..3
    const long m0  = (long)blockIdx.x * BMm;

    float acc[2][8][4];
#pragma unroll
    for (int i = 0; i < 2; i++)
#pragma unroll
        for (int j = 0; j < 8; j++)
#pragma unroll
            for (int k = 0; k < 4; k++) acc[i][j][k] = 0.f;

    // --- B tile loader (cp.async, swizzled; 16B = 16 fp8 or 8 bf16) ---
    auto cpB = [&](int s, int kt) {
        const uint32_t base = sb + B_OFF + (uint32_t)s * BBYTES;
#pragma unroll
        for (int t = 0; t < BBYTES / 16 / THREADS; t++) {
            const int idx = tid + t * THREADS;
            const int row = idx >> 3, c = idx & 7;
            const uint32_t off = (uint32_t)row * 128u +
                                 ((uint32_t)(c ^ (row & 7)) << 4);
            const void* src = (MODE == 1)
                ? (const void*)(g_fT8 + (size_t)row * NN + (size_t)kt * 128 + c * 16)
                : (const void*)(g_B2  + (size_t)row * K2 + (size_t)kt * 64  + c * 8);
            cp16(base + off, src);
        }
    };
    // --- A tile loader, MODE2 (bf16 g_A2 via cp.async) ---
    auto cpA2 = [&](int s, int kt) {
        const uint32_t base = sb + A_OFF + (uint32_t)s * ABYTES;
#pragma unroll
        for (int t = 0; t < ABYTES / 16 / THREADS; t++) {
            const int idx = tid + t * THREADS;
            const int row = idx >> 3, c = idx & 7;
            const uint32_t off = (uint32_t)row * 128u +
                                 ((uint32_t)(c ^ (row & 7)) << 4);
            cp16(base + off, g_A2 + (m0 + row) * (size_t)K2 + (size_t)kt * 64 + c * 8);
        }
    };

    // --- A tile register staging, MODE1 (f32 adj streaming LDG -> e4m3) ---
    uint32_t rQ[8];                     // 32 e4m3 bytes (this thread's slice)
    float    rowsum = 0.f;
    const int arow = tid >> 2;          // 0..63 (4 threads per row)
    const int aq   = tid & 3;           // cols aq*32 .. aq*32+31
    auto ldgA = [&](int kt) {
        const float* src = adjF + (m0 + arow) * (long)NN + (long)kt * BK + aq * 32;
#pragma unroll
        for (int j = 0; j < 8; j++) {
            float4 v = ldcs4(src + j * 4);
            rowsum += (v.x + v.y) + (v.z + v.w);     // exact f32 degree
            rQ[j] = pack4_e4m3(v.x, v.y, v.z, v.w);
        }
    };
    auto stsA = [&](int s) {
        const uint32_t base = sb + A_OFF + (uint32_t)s * ABYTES + (uint32_t)arow * 128u;
        const int rs = arow & 7;
        sts128(base + ((uint32_t)((aq * 2)     ^ rs) << 4), rQ[0], rQ[1], rQ[2], rQ[3]);
        sts128(base + ((uint32_t)((aq * 2 + 1) ^ rs) << 4), rQ[4], rQ[5], rQ[6], rQ[7]);
    };

    // --- ldmatrix thread addressing (canonical recipe; 32B per mma k-step) ---
    const int lhi  = lane >> 4;                       // chunk parity
    const int a_r0 = wm * 32 + (lane & 15);           // + mi*16
    const int b_r0 = wn * 64 + (lane & 15);           // + nb*16

    auto compute = [&](int sa, int sbg) {
        const uint32_t aBase = sb + A_OFF + (uint32_t)sa * ABYTES;
        const uint32_t bBase = sb + B_OFF + (uint32_t)sbg * BBYTES;
#pragma unroll
        for (int ks = 0; ks < 4; ks++) {              // 4 k-steps per tile
            uint32_t af[2][4], bf[4][4];
#pragma unroll
            for (int mi = 0; mi < 2; mi++) {
                const int row = a_r0 + mi * 16;
                const uint32_t addr = aBase + (uint32_t)row * 128u +
                    ((uint32_t)((ks * 2 + lhi) ^ (row & 7)) << 4);
                ldsm4(af[mi], addr);
            }
#pragma unroll
            for (int nb = 0; nb < 4; nb++) {
                const int row = b_r0 + nb * 16;
                const uint32_t addr = bBase + (uint32_t)row * 128u +
                    ((uint32_t)((ks * 2 + lhi) ^ (row & 7)) << 4);
                ldsm4(bf[nb], addr);
            }
#pragma unroll
            for (int mi = 0; mi < 2; mi++)
#pragma unroll
                for (int nb = 0; nb < 4; nb++) {
                    if constexpr (MODE == 1) {
                        mma_fp8(acc[mi][nb * 2],     af[mi], bf[nb][0], bf[nb][2]);
                        mma_fp8(acc[mi][nb * 2 + 1], af[mi], bf[nb][1], bf[nb][3]);
                    } else {
                        mma_bf16(acc[mi][nb * 2],     af[mi], bf[nb][0], bf[nb][2]);
                        mma_bf16(acc[mi][nb * 2 + 1], af[mi], bf[nb][1], bf[nb][3]);
                    }
                }
        }
    };

    // ---------------- prologue: commit PREF groups --------------------------
    if constexpr (MODE == 1) {
        ldgA(0); stsA(0);               // tile 0 A into stage 0
        ldgA(1);                        // tile 1 A staged in regs
        cpB(0, 0); cp_commit();
        cpB(1, 1); cp_commit();
    } else {
        cpA2(0, 0); cpB(0, 0); cp_commit();
        cpA2(1, 1); cpB(1, 1); cp_commit();
        cpA2(2, 2); cpB(2, 2); cp_commit();
    }

    // ---------------- main loop ----------------
    // Invariant at top of iter kt: committed groups = tiles {kt .. kt+PREF-1}.
    // wait<PREF-1> -> tile kt complete. Refill target stage (kt+PREF)%BSTG ==
    // (kt-1)%BSTG was read in compute(kt-1); the top barrier proves all warps
    // finished it.
    int sbi = 0;                        // stage of tile kt (kt % BSTG)
    for (int kt = 0; kt < KT; kt++) {
        cp_wait<PREF - 1>();
        __syncthreads();
        if (kt + PREF < KT) {
            int sn = sbi + PREF; if (sn >= BSTG) sn -= BSTG;
            if constexpr (MODE == 2) cpA2(sn, kt + PREF);
            cpB(sn, kt + PREF);
        }
        cp_commit();                    // exactly one group per iteration
        if constexpr (MODE == 1) {
            if (kt + 1 < KT) stsA((kt + 1) & 1);   // rQ holds tile kt+1
            if (kt + 2 < KT) ldgA(kt + 2);
        }
        compute((MODE == 1) ? (kt & 1) : sbi, sbi);
        sbi++; if (sbi == BSTG) sbi = 0;
    }

    // ---------------- epilogue ----------------
    if constexpr (MODE == 1) {
        rowsum += __shfl_xor_sync(0xFFFFFFFFu, rowsum, 1);
        rowsum += __shfl_xor_sync(0xFFFFFFFFu, rowsum, 2);
        if ((tid & 3) == 0) sdeg[tid >> 2] = 1.0f / (rowsum + 1.0f);
        __syncthreads();
    }

#pragma unroll
    for (int mi = 0; mi < 2; mi++) {
        const int rl = wm * 32 + mi * 16 + (lane >> 2);
        const float slo = (MODE == 1) ? sdeg[rl]     : 1.f;
        const float shi = (MODE == 1) ? sdeg[rl + 8] : 1.f;
        const long glo = m0 + rl, ghi = glo + 8;
#pragma unroll
        for (int ni = 0; ni < 8; ni++) {
            const int col = wn * 64 + ni * 8 + (lane & 3) * 2;
            const float* a = acc[mi][ni];
            if constexpr (MODE == 1) {
                *reinterpret_cast<uint32_t*>(g_A2 + glo * K2 + 768 + col) =
                    packbf2(a[0] * slo, a[1] * slo);
                *reinterpret_cast<uint32_t*>(g_A2 + ghi * K2 + 768 + col) =
                    packbf2(a[2] * shi, a[3] * shi);
            } else {
                *reinterpret_cast<float2*>(outF + glo * DF + col) =
                    make_float2(a[0], a[1]);
                *reinterpret_cast<float2*>(outF + ghi * DF + col) =
                    make_float2(a[2], a[3]);
            }
        }
    }
}

static constexpr uint32_t SMEM1 = 2 * (64  * 128) + 3 * BBYTES + 128; // ~112.1 KB
static constexpr uint32_t SMEM2 = 4 * (128 * 128) + 4 * BBYTES + 128; // ~192.1 KB

// ---------------- launch -----------------------------------------------------
extern "C" void kernel_launch(void* const* d_in, const int* in_sizes, int n_in,
                              void* d_out, int out_size) {
    const float* features = nullptr;
    const float* adj      = nullptr;
    const float* W        = nullptr;
    for (int i = 0; i < n_in; i++) {
        if (in_sizes[i] == NN * DF)          features = (const float*)d_in[i];
        else if (in_sizes[i] == DF * 2 * DF) W        = (const float*)d_in[i];
        else                                  adj      = (const float*)d_in[i];
    }

    cudaFuncSetAttribute(gemm_mma<1>, cudaFuncAttributeMaxDynamicSharedMemorySize, SMEM1);
    cudaFuncSetAttribute(gemm_mma<2>, cudaFuncAttributeMaxDynamicSharedMemorySize, SMEM2);

    prep_fT8<<<dim3(NN / 32, DF / 32), dim3(32, 8)>>>(features);
    prep_A2<<<NN, 256>>>(features);
    prep_W<<<DF, 256>>>(W);
    gemm_mma<1><<<NN / 64, 256, SMEM1>>>(nullptr, adj);
    gemm_mma<2><<<NN / 128, 512, SMEM2>>>((float*)d_out, nullptr);
}

// round 10
// speedup vs baseline: 1.3308x; 1.3308x over previous
#include <cuda_runtime.h>
#include <cuda_bf16.h>
#include <cstdint>

#define DEVINL __device__ __forceinline__

static constexpr int NN = 16384;   // nodes
static constexpr int DF = 256;     // feature dim == out dim
static constexpr int K2 = 1024;    // GEMM2 K: [f_hi | f_hi | f_lo | neigh]

// ---------------- scratch (device globals; no allocation allowed) -----------
__device__ __align__(128) __nv_bfloat16 g_fT[(size_t)DF * NN];   // 8 MB  features^T bf16
__device__ __align__(128) __nv_bfloat16 g_A2[(size_t)NN * K2];   // 32 MB GEMM2 A operand
__device__ __align__(128) __nv_bfloat16 g_B2[(size_t)DF * K2];   // 512 KB GEMM2 B operand

// ---------------- PTX helpers (all legal at compute_103 virtual arch) -------
DEVINL uint32_t smem_u32(const void* p) {
    uint32_t a;
    asm("{ .reg .u64 t; cvta.to.shared.u64 t, %1; cvt.u32.u64 %0, t; }"
        : "=r"(a) : "l"(p));
    return a;
}
DEVINL void cp16(uint32_t dst, const void* src) {
    asm volatile("cp.async.cg.shared.global [%0], [%1], 16;"
                 :: "r"(dst), "l"(src) : "memory");
}
DEVINL void cp_commit() { asm volatile("cp.async.commit_group;" ::: "memory"); }
template <int N> DEVINL void cp_wait() {
    asm volatile("cp.async.wait_group %0;" :: "n"(N) : "memory");
}
DEVINL void ldsm4(uint32_t* r, uint32_t a) {
    asm volatile("ldmatrix.sync.aligned.m8n8.x4.shared.b16 {%0,%1,%2,%3}, [%4];"
                 : "=r"(r[0]), "=r"(r[1]), "=r"(r[2]), "=r"(r[3]) : "r"(a));
}
DEVINL void sts128(uint32_t a, uint32_t x, uint32_t y, uint32_t z, uint32_t w) {
    asm volatile("st.shared.v4.b32 [%0], {%1,%2,%3,%4};"
                 :: "r"(a), "r"(x), "r"(y), "r"(z), "r"(w));
}
DEVINL void mma16816(float* d, const uint32_t* a, uint32_t b0, uint32_t b1) {
    asm volatile(
        "mma.sync.aligned.m16n8k16.row.col.f32.bf16.bf16.f32 "
        "{%0,%1,%2,%3}, {%4,%5,%6,%7}, {%8,%9}, {%0,%1,%2,%3};"
        : "+f"(d[0]), "+f"(d[1]), "+f"(d[2]), "+f"(d[3])
        : "r"(a[0]), "r"(a[1]), "r"(a[2]), "r"(a[3]), "r"(b0), "r"(b1));
}
DEVINL uint32_t packbf2(float x, float y) {
    __nv_bfloat162 h = __floats2bfloat162_rn(x, y);
    return *reinterpret_cast<uint32_t*>(&h);
}
DEVINL float4 ldcs4(const float* p) {
    float4 v;
    asm volatile("ld.global.cs.v4.f32 {%0,%1,%2,%3}, [%4];"
                 : "=f"(v.x), "=f"(v.y), "=f"(v.z), "=f"(v.w) : "l"(p));
    return v;
}

// ---------------- prep kernels ----------------------------------------------

// features^T (bf16) via tiled transpose. grid(512, 8), block(32, 8)
__global__ void prep_fT(const float* __restrict__ f) {
    __shared__ __nv_bfloat16 tile[32][33];
    const int i0 = blockIdx.x * 32, d0 = blockIdx.y * 32;
    const int tx = threadIdx.x, ty = threadIdx.y;
#pragma unroll
    for (int k = 0; k < 32; k += 8)
        tile[ty + k][tx] = __float2bfloat16(f[(size_t)(i0 + ty + k) * DF + d0 + tx]);
    __syncthreads();
#pragma unroll
    for (int k = 0; k < 32; k += 8)
        g_fT[(size_t)(d0 + ty + k) * NN + i0 + tx] = tile[tx][ty + k];
}

// A2 = [f_hi | f_hi | f_lo | (neigh filled by GEMM1 epilogue)]
__global__ void __launch_bounds__(256) prep_A2(const float* __restrict__ f) {
    const int i = blockIdx.x, d = threadIdx.x;
    const float v = f[(size_t)i * DF + d];
    const __nv_bfloat16 h = __float2bfloat16(v);
    const size_t b = (size_t)i * K2;
    g_A2[b + d]       = h;
    g_A2[b + 256 + d] = h;
    g_A2[b + 512 + d] = __float2bfloat16(v - __bfloat162float(h));
}

// B2 = [W1_hi | W1_lo | W1_hi | W2]
__global__ void __launch_bounds__(256) prep_W(const float* __restrict__ W) {
    const int o = blockIdx.x, c = threadIdx.x;
    const float w1 = W[(size_t)o * 512 + c];
    const __nv_bfloat16 h = __float2bfloat16(w1);
    const size_t b = (size_t)o * K2;
    g_B2[b + c]       = h;
    g_B2[b + 256 + c] = __float2bfloat16(w1 - __bfloat162float(h));
    g_B2[b + 512 + c] = h;
    g_B2[b + 768 + c] = __float2bfloat16(W[(size_t)o * 512 + 256 + c]);
}

// ---------------- mma.sync GEMM ----------------------------------------------
// MODE 1: BM=64,  BN=256, 256 thr (8 warps, 2Mx4N, warp tile 32x64), 2 CTAs/SM.
//         C = bf16(adj_f32) @ fT^T; fused row-sum -> inv_deg; epilogue scales,
//         writes bf16 neigh into g_A2[:, 768:1024].  A: 2-stage LDG->cvt->STS
//         (prefetch held as packed bf16), B: 3-stage cp.async, wait_group<1>.
// MODE 2: BM=128, BN=256, 512 thr (16 warps), 1 CTA/SM, 4-stage both operands.
//         C = A2 @ B2^T (K=1024 hi/lo split); epilogue writes fp32 out.
static constexpr int BN = 256, BK = 64;
static constexpr int BBYTES = BN * BK * 2;                   // 32 KB / stage

template <int MODE>
__global__ void __launch_bounds__((MODE == 1) ? 256 : 512, (MODE == 1) ? 2 : 1)
gemm_mma(float* __restrict__ outF, const float* __restrict__ adjF) {
    constexpr int  THREADS = (MODE == 1) ? 256 : 512;
    constexpr int  BMm     = (MODE == 1) ? 64  : 128;
    constexpr int  KT      = (MODE == 1) ? (NN / BK) : (K2 / BK);
    constexpr long ldb     = (MODE == 1) ? NN : K2;
    constexpr int  ASTG    = (MODE == 1) ? 2 : 4;
    constexpr int  BSTG    = (MODE == 1) ? 3 : 4;
    constexpr int  PREF    = (MODE == 1) ? 2 : 3;   // groups committed ahead
    constexpr int  ABYTES  = BMm * BK * 2;          // 8 KB / 16 KB
    constexpr uint32_t A_OFF = 0;
    constexpr uint32_t B_OFF = ASTG * ABYTES;
    const __nv_bfloat16* __restrict__ Bg = (MODE == 1) ? g_fT : g_B2;

    extern __shared__ char smraw[];
    __shared__ float sdeg[BMm];
    const uint32_t sb = (smem_u32(smraw) + 127u) & ~127u;

    const int tid  = threadIdx.x;
    const int lane = tid & 31;
    const int w    = tid >> 5;
    const int wm   = w >> 2;            // M dir: mode1 0..1, mode2 0..3
    const int wn   = w & 3;             // N dir: 0..3
    const long m0  = (long)blockIdx.x * BMm;

    float acc[2][8][4];
#pragma unroll
    for (int i = 0; i < 2; i++)
#pragma unroll
        for (int j = 0; j < 8; j++)
#pragma unroll
            for (int k = 0; k < 4; k++) acc[i][j][k] = 0.f;

    // --- B tile loader (cp.async, bf16, swizzled) ---
    auto cpB = [&](int s, int kt) {
        const long k0 = (long)kt * BK;
        const uint32_t base = sb + B_OFF + (uint32_t)s * BBYTES;
#pragma unroll
        for (int t = 0; t < BBYTES / 16 / THREADS; t++) {
            const int idx = tid + t * THREADS;
            const int row = idx >> 3, c = idx & 7;
            const uint32_t off = (uint32_t)row * 128u +
                                 ((uint32_t)(c ^ (row & 7)) << 4);
            cp16(base + off, Bg + (long)row * ldb + k0 + c * 8);
        }
    };
    // --- A tile loader, MODE2 (bf16 g_A2 via cp.async) ---
    auto cpA2 = [&](int s, int kt) {
        const long k0 = (long)kt * BK;
        const uint32_t base = sb + A_OFF + (uint32_t)s * ABYTES;
#pragma unroll
        for (int t = 0; t < ABYTES / 16 / THREADS; t++) {
            const int idx = tid + t * THREADS;
            const int row = idx >> 3, c = idx & 7;
            const uint32_t off = (uint32_t)row * 128u +
                                 ((uint32_t)(c ^ (row & 7)) << 4);
            cp16(base + off, g_A2 + (m0 + row) * (size_t)K2 + k0 + c * 8);
        }
    };

    // --- A staging, MODE1: LDG f32 -> rowsum + packed bf16 regs -> STS ------
    uint32_t rP[8];                     // 16 bf16 (packed) = this thread's slice
    float    rowsum = 0.f;
    const int arow = tid >> 2;          // 0..63 (4 threads per row)
    const int aq   = tid & 3;           // cols aq*16 .. aq*16+15
    auto ldgA = [&](int kt) {
        const float* src = adjF + (m0 + arow) * (long)NN + (long)kt * BK + aq * 16;
#pragma unroll
        for (int j = 0; j < 4; j++) {
            float4 v = ldcs4(src + j * 4);
            rowsum += (v.x + v.y) + (v.z + v.w);     // exact f32 degree
            rP[2 * j]     = packbf2(v.x, v.y);
            rP[2 * j + 1] = packbf2(v.z, v.w);
        }
    };
    auto stsA = [&](int s) {
        const uint32_t base = sb + A_OFF + (uint32_t)s * ABYTES + (uint32_t)arow * 128u;
        const int rs = arow & 7;
        sts128(base + ((uint32_t)((aq * 2)     ^ rs) << 4), rP[0], rP[1], rP[2], rP[3]);
        sts128(base + ((uint32_t)((aq * 2 + 1) ^ rs) << 4), rP[4], rP[5], rP[6], rP[7]);
    };

    // --- ldmatrix thread addressing ------------------------------------------
    // addr = stageBase + row*128 + ((c ^ (row&7))<<4), c = ks*2 + lhi.
    // row*128 | ((row&7)<<4) is c-independent -> addr = P ^ (c<<4) since the
    // XOR field (bits 4..6) is disjoint from P's c-bits. Precompute P per frag.
    const int lhi  = lane >> 4;                       // chunk parity
    const int a_r0 = wm * 32 + (lane & 15);           // + mi*16
    const int b_r0 = wn * 64 + (lane & 15);           // + nb*16

    auto compute = [&](int sa, int sbg, int ks0, int ks1) {
        const uint32_t aBase = sb + A_OFF + (uint32_t)sa * ABYTES;
        const uint32_t bBase = sb + B_OFF + (uint32_t)sbg * BBYTES;
        uint32_t Pa[2], Pb[4];
#pragma unroll
        for (int mi = 0; mi < 2; mi++) {
            const int row = a_r0 + mi * 16;
            Pa[mi] = (aBase + (uint32_t)row * 128u) | ((uint32_t)(row & 7) << 4);
        }
#pragma unroll
        for (int nb = 0; nb < 4; nb++) {
            const int row = b_r0 + nb * 16;
            Pb[nb] = (bBase + (uint32_t)row * 128u) | ((uint32_t)(row & 7) << 4);
        }
#pragma unroll
        for (int ks = ks0; ks < ks1; ks++) {
            const uint32_t cx = (uint32_t)(ks * 2 + lhi) << 4;
            uint32_t af[2][4], bf[4][4];
#pragma unroll
            for (int mi = 0; mi < 2; mi++) ldsm4(af[mi], Pa[mi] ^ cx);
#pragma unroll
            for (int nb = 0; nb < 4; nb++) ldsm4(bf[nb], Pb[nb] ^ cx);
#pragma unroll
            for (int mi = 0; mi < 2; mi++)
#pragma unroll
                for (int nb = 0; nb < 4; nb++) {
                    mma16816(acc[mi][nb * 2],     af[mi], bf[nb][0], bf[nb][2]);
                    mma16816(acc[mi][nb * 2 + 1], af[mi], bf[nb][1], bf[nb][3]);
                }
        }
    };

    // ---------------- prologue: commit PREF groups --------------------------
    if constexpr (MODE == 1) {
        ldgA(0); stsA(0);               // tile 0 A into stage 0
        ldgA(1);                        // tile 1 A staged in regs (packed)
        cpB(0, 0); cp_commit();
        cpB(1, 1); cp_commit();
    } else {
        cpA2(0, 0); cpB(0, 0); cp_commit();
        cpA2(1, 1); cpB(1, 1); cp_commit();
        cpA2(2, 2); cpB(2, 2); cp_commit();
    }

    // ---------------- main loop ----------------
    // Invariant at top of iter kt: committed groups = tiles {kt .. kt+PREF-1}.
    // wait<PREF-1> -> tile kt complete. Refill target stage (kt+PREF)%BSTG ==
    // (kt-1)%BSTG was last read in compute(kt-1); the top barrier proves all
    // warps finished it. stsA target stage (kt+1)%2: its old content (tile
    // kt-1) was also last read in compute(kt-1) -> same barrier covers it.
    // Loads are issued mid-tile (between ks 0-1 and ks 2-3) to spread L1/LSU
    // pressure across the iteration instead of bursting at the barrier.
    int sbi = 0;                        // stage of tile kt (kt % BSTG)
    for (int kt = 0; kt < KT; kt++) {
        cp_wait<PREF - 1>();
        __syncthreads();
        const int sa = (MODE == 1) ? (kt & 1) : sbi;
        compute(sa, sbi, 0, 2);                     // ks 0,1 (data resident)
        if (kt + PREF < KT) {
            int sn = sbi + PREF; if (sn >= BSTG) sn -= BSTG;
            if constexpr (MODE == 2) cpA2(sn, kt + PREF);
            cpB(sn, kt + PREF);
        }
        cp_commit();                    // exactly one group per iteration
        if constexpr (MODE == 1) {
            if (kt + 1 < KT) stsA((kt + 1) & 1);   // rP holds tile kt+1
            if (kt + 2 < KT) ldgA(kt + 2);
        }
        compute(sa, sbi, 2, 4);                     // ks 2,3
        sbi++; if (sbi == BSTG) sbi = 0;
    }

    // ---------------- epilogue ----------------
    if constexpr (MODE == 1) {
        rowsum += __shfl_xor_sync(0xFFFFFFFFu, rowsum, 1);
        rowsum += __shfl_xor_sync(0xFFFFFFFFu, rowsum, 2);
        if ((tid & 3) == 0) sdeg[tid >> 2] = 1.0f / (rowsum + 1.0f);
        __syncthreads();
    }

#pragma unroll
    for (int mi = 0; mi < 2; mi++) {
        const int rl = wm * 32 + mi * 16 + (lane >> 2);
        const float slo = (MODE == 1) ? sdeg[rl]     : 1.f;
        const float shi = (MODE == 1) ? sdeg[rl + 8] : 1.f;
        const long glo = m0 + rl, ghi = glo + 8;
#pragma unroll
        for (int ni = 0; ni < 8; ni++) {
            const int col = wn * 64 + ni * 8 + (lane & 3) * 2;
            const float* a = acc[mi][ni];
            if constexpr (MODE == 1) {
                *reinterpret_cast<uint32_t*>(g_A2 + glo * K2 + 768 + col) =
                    packbf2(a[0] * slo, a[1] * slo);
                *reinterpret_cast<uint32_t*>(g_A2 + ghi * K2 + 768 + col) =
                    packbf2(a[2] * shi, a[3] * shi);
            } else {
                *reinterpret_cast<float2*>(outF + glo * DF + col) =
                    make_float2(a[0], a[1]);
                *reinterpret_cast<float2*>(outF + ghi * DF + col) =
                    make_float2(a[2], a[3]);
            }
        }
    }
}

static constexpr uint32_t SMEM1 = 2 * (64  * BK * 2) + 3 * BBYTES + 128; // ~112.1 KB
static constexpr uint32_t SMEM2 = 4 * (128 * BK * 2) + 4 * BBYTES + 128; // ~192.1 KB

// ---------------- launch -----------------------------------------------------
extern "C" void kernel_launch(void* const* d_in, const int* in_sizes, int n_in,
                              void* d_out, int out_size) {
    const float* features = nullptr;
    const float* adj      = nullptr;
    const float* W        = nullptr;
    for (int i = 0; i < n_in; i++) {
        if (in_sizes[i] == NN * DF)          features = (const float*)d_in[i];
        else if (in_sizes[i] == DF * 2 * DF) W        = (const float*)d_in[i];
        else                                  adj      = (const float*)d_in[i];
    }

    cudaFuncSetAttribute(gemm_mma<1>, cudaFuncAttributeMaxDynamicSharedMemorySize, SMEM1);
    cudaFuncSetAttribute(gemm_mma<2>, cudaFuncAttributeMaxDynamicSharedMemorySize, SMEM2);

    prep_fT<<<dim3(NN / 32, DF / 32), dim3(32, 8)>>>(features);
    prep_A2<<<NN, 256>>>(features);
    prep_W<<<DF, 256>>>(W);
    gemm_mma<1><<<NN / 64, 256, SMEM1>>>(nullptr, adj);
    gemm_mma<2><<<NN / 128, 512, SMEM2>>>((float*)d_out, nullptr);
}

// round 11
// speedup vs baseline: 1.3888x; 1.0436x over previous
#include <cuda_runtime.h>
#include <cuda_bf16.h>
#include <cstdint>

#define DEVINL __device__ __forceinline__

static constexpr int NN = 16384;   // nodes
static constexpr int DF = 256;     // feature dim == out dim
static constexpr int K2 = 1024;    // GEMM2 K: [f_hi | f_hi | f_lo | neigh]

// ---------------- scratch (device globals; no allocation allowed) -----------
__device__ __align__(128) __nv_bfloat16 g_fT[(size_t)DF * NN];   // 8 MB  features^T bf16
__device__ __align__(128) __nv_bfloat16 g_A2[(size_t)NN * K2];   // 32 MB GEMM2 A operand
__device__ __align__(128) __nv_bfloat16 g_B2[(size_t)DF * K2];   // 512 KB GEMM2 B operand

// ---------------- PTX helpers (all legal at compute_103 virtual arch) -------
DEVINL uint32_t smem_u32(const void* p) {
    uint32_t a;
    asm("{ .reg .u64 t; cvta.to.shared.u64 t, %1; cvt.u32.u64 %0, t; }"
        : "=r"(a) : "l"(p));
    return a;
}
DEVINL void cp16(uint32_t dst, const void* src) {
    asm volatile("cp.async.cg.shared.global [%0], [%1], 16;"
                 :: "r"(dst), "l"(src) : "memory");
}
DEVINL void cp_commit() { asm volatile("cp.async.commit_group;" ::: "memory"); }
template <int N> DEVINL void cp_wait() {
    asm volatile("cp.async.wait_group %0;" :: "n"(N) : "memory");
}
DEVINL void ldsm4(uint32_t* r, uint32_t a) {
    asm volatile("ldmatrix.sync.aligned.m8n8.x4.shared.b16 {%0,%1,%2,%3}, [%4];"
                 : "=r"(r[0]), "=r"(r[1]), "=r"(r[2]), "=r"(r[3]) : "r"(a));
}
DEVINL void sts128(uint32_t a, uint32_t x, uint32_t y, uint32_t z, uint32_t w) {
    asm volatile("st.shared.v4.b32 [%0], {%1,%2,%3,%4};"
                 :: "r"(a), "r"(x), "r"(y), "r"(z), "r"(w));
}
DEVINL void mma16816(float* d, const uint32_t* a, uint32_t b0, uint32_t b1) {
    asm volatile(
        "mma.sync.aligned.m16n8k16.row.col.f32.bf16.bf16.f32 "
        "{%0,%1,%2,%3}, {%4,%5,%6,%7}, {%8,%9}, {%0,%1,%2,%3};"
        : "+f"(d[0]), "+f"(d[1]), "+f"(d[2]), "+f"(d[3])
        : "r"(a[0]), "r"(a[1]), "r"(a[2]), "r"(a[3]), "r"(b0), "r"(b1));
}
DEVINL uint32_t packbf2(float x, float y) {
    __nv_bfloat162 h = __floats2bfloat162_rn(x, y);
    return *reinterpret_cast<uint32_t*>(&h);
}
DEVINL float4 ldcs4(const float* p) {
    float4 v;
    asm volatile("ld.global.cs.v4.f32 {%0,%1,%2,%3}, [%4];"
                 : "=f"(v.x), "=f"(v.y), "=f"(v.z), "=f"(v.w) : "l"(p));
    return v;
}

// ---------------- prep kernels ----------------------------------------------

// features^T (bf16) via tiled transpose. grid(512, 8), block(32, 8)
__global__ void prep_fT(const float* __restrict__ f) {
    __shared__ __nv_bfloat16 tile[32][33];
    const int i0 = blockIdx.x * 32, d0 = blockIdx.y * 32;
    const int tx = threadIdx.x, ty = threadIdx.y;
#pragma unroll
    for (int k = 0; k < 32; k += 8)
        tile[ty + k][tx] = __float2bfloat16(f[(size_t)(i0 + ty + k) * DF + d0 + tx]);
    __syncthreads();
#pragma unroll
    for (int k = 0; k < 32; k += 8)
        g_fT[(size_t)(d0 + ty + k) * NN + i0 + tx] = tile[tx][ty + k];
}

// A2 = [f_hi | f_hi | f_lo | (neigh filled by GEMM1 epilogue)]
__global__ void __launch_bounds__(256) prep_A2(const float* __restrict__ f) {
    const int i = blockIdx.x, d = threadIdx.x;
    const float v = f[(size_t)i * DF + d];
    const __nv_bfloat16 h = __float2bfloat16(v);
    const size_t b = (size_t)i * K2;
    g_A2[b + d]       = h;
    g_A2[b + 256 + d] = h;
    g_A2[b + 512 + d] = __float2bfloat16(v - __bfloat162float(h));
}

// B2 = [W1_hi | W1_lo | W1_hi | W2]
__global__ void __launch_bounds__(256) prep_W(const float* __restrict__ W) {
    const int o = blockIdx.x, c = threadIdx.x;
    const float w1 = W[(size_t)o * 512 + c];
    const __nv_bfloat16 h = __float2bfloat16(w1);
    const size_t b = (size_t)o * K2;
    g_B2[b + c]       = h;
    g_B2[b + 256 + c] = __float2bfloat16(w1 - __bfloat162float(h));
    g_B2[b + 512 + c] = h;
    g_B2[b + 768 + c] = __float2bfloat16(W[(size_t)o * 512 + 256 + c]);
}

// ---------------- mma.sync GEMM ----------------------------------------------
// MODE 1: BM=64,  BN=256, 256 thr (8 warps, 2Mx4N, warp tile 32x64), 2 CTAs/SM.
//         C = bf16(adj_f32) @ fT^T; fused row-sum -> inv_deg; epilogue scales,
//         writes bf16 neigh into g_A2[:, 768:1024].  A: 2-stage LDG->cvt->STS,
//         B: 3-stage cp.async, wait_group<1>.
// MODE 2: BM=128, BN=256, 512 thr (16 warps), 1 CTA/SM, 4-stage both operands.
//         C = A2 @ B2^T (K=1024 hi/lo split); epilogue writes fp32 out.
// All loader addresses are carried induction variables: gmem pointers advance
// by a constant per tile, smem stage cursors rotate by stage size; swizzled
// per-thread offsets are computed once (t-strides are multiples of 8 rows, so
// the (row&7) swizzle term is t-invariant).
static constexpr int BN = 256, BK = 64;
static constexpr int BBYTES = BN * BK * 2;                   // 32 KB / stage

template <int MODE>
__global__ void __launch_bounds__((MODE == 1) ? 256 : 512, (MODE == 1) ? 2 : 1)
gemm_mma(float* __restrict__ outF, const float* __restrict__ adjF) {
    constexpr int  THREADS = (MODE == 1) ? 256 : 512;
    constexpr int  BMm     = (MODE == 1) ? 64  : 128;
    constexpr int  KT      = (MODE == 1) ? (NN / BK) : (K2 / BK);
    constexpr long ldb     = (MODE == 1) ? NN : K2;
    constexpr int  ASTG    = (MODE == 1) ? 2 : 4;
    constexpr int  BSTG    = (MODE == 1) ? 3 : 4;
    constexpr int  PREF    = (MODE == 1) ? 2 : 3;   // groups committed ahead
    constexpr int  ABYTES  = BMm * BK * 2;          // 8 KB / 16 KB
    constexpr int  NB_T    = BBYTES / 16 / THREADS; // 8 / 4
    constexpr int  NA_T    = ABYTES / 16 / THREADS; // (mode2) 2
    constexpr int  RSTRIDE = THREADS / 8;           // rows per t-step (32 / 64)
    constexpr uint32_t A_OFF = 0;
    constexpr uint32_t B_OFF = ASTG * ABYTES;
    const __nv_bfloat16* __restrict__ Bg = (MODE == 1) ? g_fT : g_B2;

    extern __shared__ char smraw[];
    __shared__ float sdeg[BMm];
    const uint32_t sb = (smem_u32(smraw) + 127u) & ~127u;

    const int tid  = threadIdx.x;
    const int lane = tid & 31;
    const int w    = tid >> 5;
    const int wm   = w >> 2;            // M dir: mode1 0..1, mode2 0..3
    const int wn   = w & 3;             // N dir: 0..3
    const long m0  = (long)blockIdx.x * BMm;

    float acc[2][8][4];
#pragma unroll
    for (int i = 0; i < 2; i++)
#pragma unroll
        for (int j = 0; j < 8; j++)
#pragma unroll
            for (int k = 0; k < 4; k++) acc[i][j][k] = 0.f;

    // ---- B loader state (induction) ----
    const int rowB = tid >> 3, cB = tid & 7;
    const __nv_bfloat16* pBg = Bg + (size_t)rowB * ldb + cB * 8;   // next tile
    const uint32_t offB = (uint32_t)rowB * 128u +
                          ((uint32_t)(cB ^ (rowB & 7)) << 4);
    uint32_t dstB = sb + B_OFF;                                    // stage cursor
    auto cpB = [&]() {                                             // loads next tile
#pragma unroll
        for (int t = 0; t < NB_T; t++)
            cp16(dstB + offB + (uint32_t)t * (RSTRIDE * 128u),
                 pBg + (size_t)t * RSTRIDE * ldb);
        pBg  += BK;
        dstB += BBYTES;
        if (dstB == sb + B_OFF + BSTG * BBYTES) dstB = sb + B_OFF;
    };

    // ---- A loader state, MODE2 (induction) ----
    const __nv_bfloat16* pA2g = g_A2 + (m0 + rowB) * (size_t)K2 + cB * 8;
    uint32_t dstA = sb + A_OFF;
    auto cpA2 = [&]() {
#pragma unroll
        for (int t = 0; t < NA_T; t++)
            cp16(dstA + offB + (uint32_t)t * (RSTRIDE * 128u),
                 pA2g + (size_t)t * RSTRIDE * K2);
        pA2g += BK;
        dstA += ABYTES;
        if (dstA == sb + A_OFF + ASTG * ABYTES) dstA = sb + A_OFF;
    };

    // ---- A staging, MODE1: LDG f32 -> rowsum + packed bf16 regs -> STS -----
    uint32_t rP[8];                     // 16 bf16 (packed) = this thread's slice
    float    rowsum = 0.f;
    const int arow = tid >> 2;          // 0..63 (4 threads per row)
    const int aq   = tid & 3;           // cols aq*16 .. aq*16+15
    const float* pA = adjF + (m0 + arow) * (long)NN + aq * 16;     // next tile
    auto ldgA = [&]() {
#pragma unroll
        for (int j = 0; j < 4; j++) {
            float4 v = ldcs4(pA + j * 4);
            rowsum += (v.x + v.y) + (v.z + v.w);     // exact f32 degree
            rP[2 * j]     = packbf2(v.x, v.y);
            rP[2 * j + 1] = packbf2(v.z, v.w);
        }
        pA += BK;
    };
    // stsA: second chunk offset = first ^ 16 (c even -> (c+1)^rs == (c^rs)^1)
    const uint32_t sA0 = sb + A_OFF + (uint32_t)arow * 128u +
                         ((uint32_t)((aq * 2) ^ (arow & 7)) << 4);
    auto stsA = [&](int s) {
        const uint32_t a0 = sA0 + (uint32_t)s * ABYTES;
        sts128(a0,      rP[0], rP[1], rP[2], rP[3]);
        sts128(a0 ^ 16, rP[4], rP[5], rP[6], rP[7]);
    };

    // ---- ldmatrix fragment row terms (computed once) ----
    const int lhi  = lane >> 4;                       // chunk parity
    uint32_t rtA[2], rtB[4];
#pragma unroll
    for (int mi = 0; mi < 2; mi++) {
        const int row = wm * 32 + (lane & 15) + mi * 16;
        rtA[mi] = (uint32_t)row * 128u | ((uint32_t)(row & 7) << 4);
    }
#pragma unroll
    for (int nb = 0; nb < 4; nb++) {
        const int row = wn * 64 + (lane & 15) + nb * 16;
        rtB[nb] = (uint32_t)row * 128u | ((uint32_t)(row & 7) << 4);
    }

    auto compute = [&](uint32_t aBase, uint32_t bBase, int ks0, int ks1) {
#pragma unroll
        for (int ks = ks0; ks < ks1; ks++) {
            const uint32_t cx = (uint32_t)(ks * 2 + lhi) << 4;
            uint32_t af[2][4], bf[4][4];
#pragma unroll
            for (int mi = 0; mi < 2; mi++) ldsm4(af[mi], (aBase + rtA[mi]) ^ cx);
#pragma unroll
            for (int nb = 0; nb < 4; nb++) ldsm4(bf[nb], (bBase + rtB[nb]) ^ cx);
#pragma unroll
            for (int mi = 0; mi < 2; mi++)
#pragma unroll
                for (int nb = 0; nb < 4; nb++) {
                    mma16816(acc[mi][nb * 2],     af[mi], bf[nb][0], bf[nb][2]);
                    mma16816(acc[mi][nb * 2 + 1], af[mi], bf[nb][1], bf[nb][3]);
                }
        }
    };

    // ---------------- prologue: commit PREF groups --------------------------
    if constexpr (MODE == 1) {
        ldgA(); stsA(0);                // tile 0 A into stage 0
        ldgA();                         // tile 1 A staged in regs (packed)
        cpB(); cp_commit();             // tile 0 B -> stage 0
        cpB(); cp_commit();             // tile 1 B -> stage 1
    } else {
        cpA2(); cpB(); cp_commit();     // tile 0
        cpA2(); cpB(); cp_commit();     // tile 1
        cpA2(); cpB(); cp_commit();     // tile 2
    }

    // ---------------- main loop ----------------
    // Invariant at top of iter kt: committed groups = tiles {kt .. kt+PREF-1}.
    // wait<PREF-1> -> tile kt complete. Refill target stage was last read at
    // iter kt-1; the top barrier proves all warps finished it. stsA target
    // stage (kt+1)%2 was also last read at iter kt-1 -> same barrier covers it.
    uint32_t cAs = sb + A_OFF;          // compute stage cursors (tile kt)
    uint32_t cBs = sb + B_OFF;
    for (int kt = 0; kt < KT; kt++) {
        cp_wait<PREF - 1>();
        __syncthreads();
        compute(cAs, cBs, 0, 2);                    // ks 0,1 (data resident)
        if (kt + PREF < KT) {
            if constexpr (MODE == 2) cpA2();
            cpB();
        }
        cp_commit();                    // exactly one group per iteration
        if constexpr (MODE == 1) {
            if (kt + 1 < KT) stsA((kt + 1) & 1);   // rP holds tile kt+1
            if (kt + 2 < KT) ldgA();
        }
        compute(cAs, cBs, 2, 4);                    // ks 2,3
        cAs += ABYTES;
        if (cAs == sb + A_OFF + ASTG * ABYTES) cAs = sb + A_OFF;
        cBs += BBYTES;
        if (cBs == sb + B_OFF + BSTG * BBYTES) cBs = sb + B_OFF;
    }

    // ---------------- epilogue ----------------
    if constexpr (MODE == 1) {
        rowsum += __shfl_xor_sync(0xFFFFFFFFu, rowsum, 1);
        rowsum += __shfl_xor_sync(0xFFFFFFFFu, rowsum, 2);
        if ((tid & 3) == 0) sdeg[tid >> 2] = 1.0f / (rowsum + 1.0f);
        __syncthreads();
    }

#pragma unroll
    for (int mi = 0; mi < 2; mi++) {
        const int rl = wm * 32 + mi * 16 + (lane >> 2);
        const float slo = (MODE == 1) ? sdeg[rl]     : 1.f;
        const float shi = (MODE == 1) ? sdeg[rl + 8] : 1.f;
        const long glo = m0 + rl, ghi = glo + 8;
#pragma unroll
        for (int ni = 0; ni < 8; ni++) {
            const int col = wn * 64 + ni * 8 + (lane & 3) * 2;
            const float* a = acc[mi][ni];
            if constexpr (MODE == 1) {
                *reinterpret_cast<uint32_t*>(g_A2 + glo * K2 + 768 + col) =
                    packbf2(a[0] * slo, a[1] * slo);
                *reinterpret_cast<uint32_t*>(g_A2 + ghi * K2 + 768 + col) =
                    packbf2(a[2] * shi, a[3] * shi);
            } else {
                *reinterpret_cast<float2*>(outF + glo * DF + col) =
                    make_float2(a[0], a[1]);
                *reinterpret_cast<float2*>(outF + ghi * DF + col) =
                    make_float2(a[2], a[3]);
            }
        }
    }
}

static constexpr uint32_t SMEM1 = 2 * (64  * BK * 2) + 3 * BBYTES + 128; // ~112.1 KB
static constexpr uint32_t SMEM2 = 4 * (128 * BK * 2) + 4 * BBYTES + 128; // ~192.1 KB

// ---------------- launch -----------------------------------------------------
extern "C" void kernel_launch(void* const* d_in, const int* in_sizes, int n_in,
                              void* d_out, int out_size) {
    const float* features = nullptr;
    const float* adj      = nullptr;
    const float* W        = nullptr;
    for (int i = 0; i < n_in; i++) {
        if (in_sizes[i] == NN * DF)          features = (const float*)d_in[i];
        else if (in_sizes[i] == DF * 2 * DF) W        = (const float*)d_in[i];
        else                                  adj      = (const float*)d_in[i];
    }

    cudaFuncSetAttribute(gemm_mma<1>, cudaFuncAttributeMaxDynamicSharedMemorySize, SMEM1);
    cudaFuncSetAttribute(gemm_mma<2>, cudaFuncAttributeMaxDynamicSharedMemorySize, SMEM2);

    prep_fT<<<dim3(NN / 32, DF / 32), dim3(32, 8)>>>(features);
    prep_A2<<<NN, 256>>>(features);
    prep_W<<<DF, 256>>>(W);
    gemm_mma<1><<<NN / 64, 256, SMEM1>>>(nullptr, adj);
    gemm_mma<2><<<NN / 128, 512, SMEM2>>>((float*)d_out, nullptr);
}